// round 3
// baseline (speedup 1.0000x reference)
#include <cuda_runtime.h>
#include <math.h>

#define NPTS 8192
#define BB   4
#define DD   128
#define KK   8
#define NB   (NPTS*BB)        // 32768
#define NR   (NB*KK)          // 262144 rows of (point, neighbor)
#define GST  132              // padded shared stride for GEMM tiles

// ---------------- scratch (device globals: allocation-free) ----------------
__device__ float g_qf[BB*NPTS*DD];   // [B,N,D]
__device__ float g_kf[BB*NPTS*DD];
__device__ float g_vf[BB*NPTS*DD];
__device__ float g_res[BB*NPTS*DD];
__device__ int   g_idx[BB*NPTS*KK];
__device__ float g_h [NR*DD];        // h = gelu(lin1(rel)); later reused for attn logits a
__device__ float g_pe[NR*DD];        // pe = lin2(h)
__device__ float g_u [NR*DD];        // u = q - k_knn + pe

// ---------------- f32x2 packed-FMA helpers (sm_100+) ----------------
__device__ __forceinline__ unsigned long long pack2(float lo, float hi) {
    unsigned long long r;
    asm("mov.b64 %0, {%1, %2};" : "=l"(r) : "f"(lo), "f"(hi));
    return r;
}
__device__ __forceinline__ unsigned long long fma2(unsigned long long a,
                                                   unsigned long long b,
                                                   unsigned long long c) {
    unsigned long long d;
    asm("fma.rn.f32x2 %0, %1, %2, %3;" : "=l"(d) : "l"(a), "l"(b), "l"(c));
    return d;
}
__device__ __forceinline__ void unpack2(unsigned long long p, float& lo, float& hi) {
    asm("mov.b64 {%0, %1}, %2;" : "=f"(lo), "=f"(hi) : "l"(p));
}

// ============================================================================
// GEMM: [rows,128] @ [128,128] (+bias, optional residual), f32x2 inner loop.
// mode 0/1/2: A=query [N,B,D] rows, out -> g_qf/g_kf/g_vf scattered to [B,N,D]
// mode 3:     A=g_res permuted rows, out -> d_out [N,B,D] + residual
// mode 4:     A=g_h  plain rows, out -> g_pe   (pe GEMM)
// mode 5:     A=g_u  plain rows, out -> g_h    (attn-logits GEMM, reuses g_h)
// ============================================================================
__global__ __launch_bounds__(256, 1) void gemm_k(
    const float* __restrict__ Aext, const float* __restrict__ W,
    const float* __restrict__ bias, const float* __restrict__ resid,
    float* __restrict__ outext, int mode)
{
    extern __shared__ float smbuf[];
    float* Ats = smbuf;               // [128][GST], transposed: Ats[j*GST+m]
    float* Ws  = smbuf + 128*GST;     // [128][GST]

    const float* A = (mode == 3) ? (const float*)g_res :
                     (mode == 4) ? (const float*)g_h  :
                     (mode == 5) ? (const float*)g_u  : Aext;
    float* outp = (mode == 0) ? (float*)g_qf :
                  (mode == 1) ? (float*)g_kf :
                  (mode == 2) ? (float*)g_vf :
                  (mode == 4) ? (float*)g_pe :
                  (mode == 5) ? (float*)g_h  : outext;

    const int tid = threadIdx.x;
    const int m0  = blockIdx.x * 128;

    #pragma unroll 8
    for (int i = tid; i < DD*DD; i += 256) {
        int j = i >> 7, d = i & 127;
        Ws[j*GST + d] = W[i];
    }
    #pragma unroll 8
    for (int i = tid; i < 128*DD; i += 256) {
        int m = i >> 7, j = i & 127;
        int gm = m0 + m;
        int arow = (mode == 3) ? ((gm & 3) * NPTS + (gm >> 2)) : gm;
        Ats[j*GST + m] = A[(size_t)arow*DD + j];
    }
    __syncthreads();

    const int tx = tid & 15, ty = tid >> 4;
    const int r0 = ty * 8, c0 = tx * 8;

    unsigned long long acc2[4][8];
    #pragma unroll
    for (int rp = 0; rp < 4; rp++)
        #pragma unroll
        for (int c = 0; c < 8; c++) acc2[rp][c] = 0ull;

    #pragma unroll 2
    for (int j = 0; j < 128; ++j) {
        const ulonglong2 a01 = *(const ulonglong2*)(Ats + j*GST + r0);
        const ulonglong2 a45 = *(const ulonglong2*)(Ats + j*GST + r0 + 4);
        const float4 w0 = *(const float4*)(Ws + j*GST + c0);
        const float4 w1 = *(const float4*)(Ws + j*GST + c0 + 4);
        unsigned long long wd[8];
        wd[0]=pack2(w0.x,w0.x); wd[1]=pack2(w0.y,w0.y);
        wd[2]=pack2(w0.z,w0.z); wd[3]=pack2(w0.w,w0.w);
        wd[4]=pack2(w1.x,w1.x); wd[5]=pack2(w1.y,w1.y);
        wd[6]=pack2(w1.z,w1.z); wd[7]=pack2(w1.w,w1.w);
        unsigned long long av[4] = {a01.x, a01.y, a45.x, a45.y};
        #pragma unroll
        for (int rp = 0; rp < 4; rp++)
            #pragma unroll
            for (int c = 0; c < 8; c++)
                acc2[rp][c] = fma2(av[rp], wd[c], acc2[rp][c]);
    }

    float accf[8][8];
    #pragma unroll
    for (int rp = 0; rp < 4; rp++)
        #pragma unroll
        for (int c = 0; c < 8; c++)
            unpack2(acc2[rp][c], accf[2*rp][c], accf[2*rp+1][c]);

    float bv[8];
    #pragma unroll
    for (int c = 0; c < 8; c++) bv[c] = bias[c0 + c];

    #pragma unroll
    for (int r = 0; r < 8; r++) {
        int gm = m0 + r0 + r;
        float* orow;
        const float* rrow = 0;
        if (mode < 3) {
            orow = outp + (size_t)((gm & 3) * NPTS + (gm >> 2)) * DD;
        } else if (mode == 3) {
            orow = outp + (size_t)gm * DD;
            rrow = resid + (size_t)gm * DD;
        } else {
            orow = outp + (size_t)gm * DD;
        }
        #pragma unroll
        for (int c = 0; c < 8; c++) {
            float v = accf[r][c] + bv[c];
            if (mode == 3) v += rrow[c0 + c];
            orow[c0 + c] = v;
        }
    }
}

// ============================================================================
// Brute-force KNN, 4-way candidate split, BANK-CONFLICT-FREE candidate tiles:
// chunk s lives at cand[s*257 .. s*257+255] so the 4 split bases land on
// banks {0-3},{4-7},{8-11},{12-15}.
// ============================================================================
__global__ __launch_bounds__(256, 1) void knn_k(const float* __restrict__ pos)
{
    __shared__ float4 cand[1028];
    __shared__ float  sd[256*8];
    __shared__ int    si[256*8];

    const int b = blockIdx.y;
    const int t = threadIdx.x;
    const int q = blockIdx.x * 64 + (t >> 2);
    const int s = t & 3;
    const float* pb = pos + (size_t)b * NPTS * 3;

    const float qx = pb[q*3], qy = pb[q*3+1], qz = pb[q*3+2];
    const float qsq = fmaf(qz, qz, fmaf(qy, qy, qx*qx));

    float bd[8]; int bi[8];
    #pragma unroll
    for (int k = 0; k < 8; k++) { bd[k] = 1e30f; bi[k] = 0x7fffffff; }

    const int base = s * 257;
    for (int t0 = 0; t0 < NPTS; t0 += 1024) {
        __syncthreads();
        #pragma unroll
        for (int i = t; i < 1024; i += 256) {
            float x = pb[(t0+i)*3], y = pb[(t0+i)*3+1], z = pb[(t0+i)*3+2];
            cand[i + (i >> 8)] = make_float4(x, y, z, fmaf(z, z, fmaf(y, y, x*x)));
        }
        __syncthreads();
        #pragma unroll 4
        for (int m = 0; m < 256; ++m) {
            float4 c = cand[base + m];
            float dot = fmaf(qz, c.z, fmaf(qy, c.y, qx * c.x));
            float d2  = fmaf(-2.f, dot, qsq + c.w);
            if (d2 < bd[7]) {
                bd[7] = d2; bi[7] = t0 + s*256 + m;
                #pragma unroll
                for (int r = 7; r > 0; --r) {
                    if (bd[r] < bd[r-1]) {
                        float td = bd[r]; bd[r] = bd[r-1]; bd[r-1] = td;
                        int   ti = bi[r]; bi[r] = bi[r-1]; bi[r-1] = ti;
                    }
                }
            }
        }
    }

    #pragma unroll
    for (int k = 0; k < 8; k++) { sd[t*8+k] = bd[k]; si[t*8+k] = bi[k]; }
    __syncthreads();

    if (s == 0) {
        int p[4] = {0, 0, 0, 0};
        int* op = g_idx + ((size_t)b * NPTS + q) * KK;
        #pragma unroll
        for (int o = 0; o < 8; ++o) {
            float bdv = 1e38f; int biv = 0x7fffffff; int bl = 0;
            #pragma unroll
            for (int l = 0; l < 4; ++l) {
                float dv = sd[(t+l)*8 + p[l]];
                int   iv = si[(t+l)*8 + p[l]];
                if (dv < bdv || (dv == bdv && iv < biv)) { bdv = dv; biv = iv; bl = l; }
            }
            op[o] = biv;
            p[bl]++;
        }
    }
}

// ============================================================================
// build h: row r=(g,k) of [NR,128]: h = gelu(rel . Wp1[:,d] + bp1[d])
// ============================================================================
__global__ __launch_bounds__(256, 1) void buildh_k(
    const float* __restrict__ pos,
    const float* __restrict__ Wp1, const float* __restrict__ bp1)
{
    const int gid = blockIdx.x * 256 + threadIdx.x;   // element id, < NR*128
    const int r = gid >> 7, d = gid & 127;
    const int g = r >> 3;
    const int b = g >> 13, n = g & (NPTS - 1);
    const int id = g_idx[r];
    const float* pb = pos + (size_t)b * NPTS * 3;
    const float rx = pb[n*3+0] - pb[id*3+0];
    const float ry = pb[n*3+1] - pb[id*3+1];
    const float rz = pb[n*3+2] - pb[id*3+2];
    float z = fmaf(rz, Wp1[256+d], fmaf(ry, Wp1[128+d], fmaf(rx, Wp1[d], bp1[d])));
    g_h[gid] = 0.5f * z * (1.f + erff(z * 0.70710678118654752f));
}

// ============================================================================
// build u: u[r][d] = q[g][d] - kf[idx[r]][d] + pe[r][d]
// ============================================================================
__global__ __launch_bounds__(256, 1) void buildu_k()
{
    const int gid = blockIdx.x * 256 + threadIdx.x;
    const int r = gid >> 7, d = gid & 127;
    const int g = r >> 3;
    const int id = g_idx[r];
    const int b = g >> 13;
    float qv = g_qf[(size_t)g * DD + d];
    float kv = g_kf[((size_t)b * NPTS + id) * DD + d];
    g_u[gid] = qv - kv + g_pe[gid];
}

// ============================================================================
// finish: per (g,k) row softmax over d of a (= g_h after mode-5 GEMM),
// res[g][d] = sum_k sm * (v_gather + pe)
// 256 threads = 2 groups of 128 (one point per group).
// ============================================================================
__global__ __launch_bounds__(256, 1) void finish_k()
{
    __shared__ float rA[2][32];
    __shared__ float rB[2][32];

    const int tid  = threadIdx.x;
    const int grp  = tid >> 7;
    const int d    = tid & 127;
    const int lane = tid & 31;
    const int wsub = (tid >> 5) & 3;
    const int g    = blockIdx.x * 2 + grp;
    const int b    = g >> 13;
    const float scale = 0.08838834764831845f;   // 1/sqrt(128)

    float a[8];
    #pragma unroll
    for (int k = 0; k < 8; ++k)
        a[k] = g_h[((size_t)g*8 + k) * DD + d] * scale;

    float red[8];
    #pragma unroll
    for (int k = 0; k < 8; ++k) red[k] = a[k];
    #pragma unroll
    for (int off = 16; off > 0; off >>= 1)
        #pragma unroll
        for (int k = 0; k < 8; ++k)
            red[k] = fmaxf(red[k], __shfl_xor_sync(0xffffffffu, red[k], off));
    if (lane == 0) {
        #pragma unroll
        for (int k = 0; k < 8; ++k) rA[grp][wsub*8 + k] = red[k];
    }
    __syncthreads();

    float e[8];
    #pragma unroll
    for (int k = 0; k < 8; ++k) {
        float bm = fmaxf(fmaxf(rA[grp][k], rA[grp][8+k]),
                         fmaxf(rA[grp][16+k], rA[grp][24+k]));
        e[k] = __expf(a[k] - bm);
        red[k] = e[k];
    }
    #pragma unroll
    for (int off = 16; off > 0; off >>= 1)
        #pragma unroll
        for (int k = 0; k < 8; ++k)
            red[k] += __shfl_xor_sync(0xffffffffu, red[k], off);
    if (lane == 0) {
        #pragma unroll
        for (int k = 0; k < 8; ++k) rB[grp][wsub*8 + k] = red[k];
    }
    __syncthreads();

    float rsum = 0.f;
    #pragma unroll
    for (int k = 0; k < 8; ++k) {
        float tot = (rB[grp][k] + rB[grp][8+k]) + (rB[grp][16+k] + rB[grp][24+k]);
        float smx = e[k] / tot;
        int id = g_idx[(size_t)g*8 + k];
        float v  = g_vf[((size_t)b * NPTS + id) * DD + d];
        float pe = g_pe[((size_t)g*8 + k) * DD + d];
        rsum = fmaf(smx, v + pe, rsum);
    }
    g_res[(size_t)g * DD + d] = rsum;
}

// ============================================================================
// host launch
// ============================================================================
#define GEMM_SMEM (2*128*GST*4)

extern "C" void kernel_launch(void* const* d_in, const int* in_sizes, int n_in,
                              void* d_out, int out_size)
{
    const float* query = (const float*)d_in[0];
    const float* pos   = (const float*)d_in[1];
    const float* Wq  = (const float*)d_in[2];  const float* bq  = (const float*)d_in[3];
    const float* Wk  = (const float*)d_in[4];  const float* bk  = (const float*)d_in[5];
    const float* Wv  = (const float*)d_in[6];  const float* bv  = (const float*)d_in[7];
    const float* Wp1 = (const float*)d_in[8];  const float* bp1 = (const float*)d_in[9];
    const float* Wp2 = (const float*)d_in[10]; const float* bp2 = (const float*)d_in[11];
    const float* Wg  = (const float*)d_in[12]; const float* bg  = (const float*)d_in[13];
    const float* Wo  = (const float*)d_in[14]; const float* bo  = (const float*)d_in[15];
    float* out = (float*)d_out;

    cudaFuncSetAttribute(gemm_k, cudaFuncAttributeMaxDynamicSharedMemorySize, GEMM_SMEM);

    // QKV projections -> g_qf/g_kf/g_vf in [B,N,D]
    gemm_k<<<NB/128, 256, GEMM_SMEM>>>(query, Wq, bq, (const float*)0, (float*)0, 0);
    gemm_k<<<NB/128, 256, GEMM_SMEM>>>(query, Wk, bk, (const float*)0, (float*)0, 1);
    gemm_k<<<NB/128, 256, GEMM_SMEM>>>(query, Wv, bv, (const float*)0, (float*)0, 2);

    // KNN indices (4-way split per query, conflict-free tiles)
    knn_k<<<dim3(NPTS/64, BB), 256>>>(pos);

    // h = gelu(lin1(rel))          [NR,128]
    buildh_k<<<NR*DD/256, 256>>>(pos, Wp1, bp1);

    // pe = h @ Wp2 + bp2           [NR,128]
    gemm_k<<<NR/128, 256, GEMM_SMEM>>>((const float*)0, Wp2, bp2, (const float*)0, (float*)0, 4);

    // u = q - k_knn + pe           [NR,128]
    buildu_k<<<NR*DD/256, 256>>>();

    // a = u @ Wg + bg              [NR,128]  (written into g_h)
    gemm_k<<<NR/128, 256, GEMM_SMEM>>>((const float*)0, Wg, bg, (const float*)0, (float*)0, 5);

    // softmax over d + weighted sum over k -> g_res [B,N,D]
    finish_k<<<NB/2, 256>>>();

    // output projection + residual -> [N,B,D]
    gemm_k<<<NB/128, 256, GEMM_SMEM>>>(query, Wo, bo, query, out, 3);
}

// round 8
// speedup vs baseline: 1.6746x; 1.6746x over previous
#include <cuda_runtime.h>
#include <math.h>

#define NPTS 8192
#define BB   4
#define DD   128
#define KK   8
#define NB   (NPTS*BB)        // 32768
#define NR   (NB*KK)          // 262144

#define WST2 136              // W hi/lo tile word stride (rows = 64 k-pairs)
#define AST2 68               // A hi/lo tile word stride (rows = 128 m)

// smem word offsets
#define OFF_WHI 0             // 64*136  = 8704
#define OFF_WLO 8704
#define OFF_AHI 17408         // 128*68  = 8704
#define OFF_ALO 26112
#define OFF_SB  34816         // bias[128]
#define SMEM_WORDS 34944
#define SMEM_BYTES (SMEM_WORDS*4)   // 139776

// ---------------- scratch ----------------
__device__ float g_qf[BB*NPTS*DD];
__device__ float g_kf[BB*NPTS*DD];
__device__ float g_vf[BB*NPTS*DD];
__device__ float g_res[BB*NPTS*DD];
__device__ int   g_idx[BB*NPTS*KK];
__device__ float g_h [NR*DD];        // h = gelu(lin1(rel)); later reused for logits a
__device__ float g_pe[NR*DD];
__device__ float g_u [NR*DD];

// ---------------- bf16 helpers ----------------
__device__ __forceinline__ unsigned bfpack(float lo_elem, float hi_elem) {
    unsigned r;
    asm("cvt.rn.bf16x2.f32 %0, %1, %2;" : "=r"(r) : "f"(hi_elem), "f"(lo_elem));
    return r;
}
__device__ __forceinline__ void bfsplit(float x0, float x1,
                                        unsigned& hp, unsigned& lp) {
    hp = bfpack(x0, x1);
    float h0 = __uint_as_float(hp << 16);
    float h1 = __uint_as_float(hp & 0xFFFF0000u);
    lp = bfpack(x0 - h0, x1 - h1);
}
__device__ __forceinline__ void mma_bf16(float* c, const unsigned* a,
                                         unsigned b0, unsigned b1) {
    asm volatile(
        "mma.sync.aligned.m16n8k16.row.col.f32.bf16.bf16.f32 "
        "{%0,%1,%2,%3}, {%4,%5,%6,%7}, {%8,%9}, {%0,%1,%2,%3};"
        : "+f"(c[0]), "+f"(c[1]), "+f"(c[2]), "+f"(c[3])
        : "r"(a[0]), "r"(a[1]), "r"(a[2]), "r"(a[3]), "r"(b0), "r"(b1));
}

// ============================================================================
// bf16-split MMA GEMM (plain epilogues only — de-fused pipeline).
// C[128-tile] = A[.,128] @ W[128,128] + bias.  3-term:
// D = Ahi*Whi + Alo*Whi + Ahi*Wlo  (fp32 accumulate)
// Modes:
//  0/1/2: A=query rows (n*B+b), out scattered to g_qf/g_kf/g_vf [B,N,D]
//  3:     A=g_res (permuted rows), out -> d_out [N,B,D] + query residual
//  4:     A=g_h  plain rows, out -> g_pe
//  5:     A=g_u  plain rows, out -> g_h
// ============================================================================
__global__ __launch_bounds__(256, 1) void gemm_mma(
    const float* __restrict__ Aext, const float* __restrict__ W,
    const float* __restrict__ bias, const float* __restrict__ resid,
    float* __restrict__ outext, int mode)
{
    extern __shared__ unsigned smw[];
    unsigned* WhiP = smw + OFF_WHI;
    unsigned* WloP = smw + OFF_WLO;
    unsigned* AhiP = smw + OFF_AHI;
    unsigned* AloP = smw + OFF_ALO;
    float* sb = (float*)(smw + OFF_SB);

    const int tid = threadIdx.x;
    const int m0  = blockIdx.x * 128;

    // ---- W -> WhiP/WloP (bf16 split, packed along k-pairs), vectorized ----
    #pragma unroll
    for (int p = tid; p < 2048; p += 256) {
        int kk = p >> 5, nq = p & 31;       // k-pair row, col quad
        const float4 L0 = *(const float4*)(W + (2*kk    )*128 + 4*nq);
        const float4 L1 = *(const float4*)(W + (2*kk + 1)*128 + 4*nq);
        uint4 h, l;
        bfsplit(L0.x, L1.x, h.x, l.x);
        bfsplit(L0.y, L1.y, h.y, l.y);
        bfsplit(L0.z, L1.z, h.z, l.z);
        bfsplit(L0.w, L1.w, h.w, l.w);
        *(uint4*)(WhiP + kk*WST2 + 4*nq) = h;
        *(uint4*)(WloP + kk*WST2 + 4*nq) = l;
    }
    if (tid < 128) sb[tid] = bias[tid];

    // ---- A tile -> AhiP/AloP ----
    {
        const float* Aptr = (mode == 3) ? (const float*)g_res :
                            (mode == 4) ? (const float*)g_h  :
                            (mode == 5) ? (const float*)g_u  : Aext;
        #pragma unroll
        for (int i = tid; i < 4096; i += 256) {
            int m = i >> 5, cc = i & 31;
            int gm = m0 + m;
            int arow = (mode == 3) ? ((gm & 3) * NPTS + (gm >> 2)) : gm;
            float4 v = *(const float4*)(Aptr + (size_t)arow*DD + cc*4);
            uint2 h, l;
            bfsplit(v.x, v.y, h.x, l.x);
            bfsplit(v.z, v.w, h.y, l.y);
            *(uint2*)(AhiP + m*AST2 + 2*cc) = h;
            *(uint2*)(AloP + m*AST2 + 2*cc) = l;
        }
    }
    __syncthreads();

    // ---- MMA mainloop (m16n8k16 bf16, 3-term) ----
    const int lane  = tid & 31;
    const int wid   = tid >> 5;
    const int warpM = (wid & 3) * 32;
    const int warpN = (wid >> 2) * 64;
    const int gid   = lane >> 2;
    const int tig   = lane & 3;

    float acc[2][8][4];
    #pragma unroll
    for (int mt = 0; mt < 2; mt++)
        #pragma unroll
        for (int nt = 0; nt < 8; nt++)
            #pragma unroll
            for (int q = 0; q < 4; q++) acc[mt][nt][q] = 0.f;

    #pragma unroll 1
    for (int ks = 0; ks < 8; ++ks) {
        const int kk0 = ks * 8;
        unsigned ahi[2][4], alo[2][4];
        #pragma unroll
        for (int mt = 0; mt < 2; mt++) {
            const int r0 = warpM + mt*16 + gid;
            ahi[mt][0] = AhiP[(r0    )*AST2 + kk0 + tig];
            ahi[mt][1] = AhiP[(r0 + 8)*AST2 + kk0 + tig];
            ahi[mt][2] = AhiP[(r0    )*AST2 + kk0 + tig + 4];
            ahi[mt][3] = AhiP[(r0 + 8)*AST2 + kk0 + tig + 4];
            alo[mt][0] = AloP[(r0    )*AST2 + kk0 + tig];
            alo[mt][1] = AloP[(r0 + 8)*AST2 + kk0 + tig];
            alo[mt][2] = AloP[(r0    )*AST2 + kk0 + tig + 4];
            alo[mt][3] = AloP[(r0 + 8)*AST2 + kk0 + tig + 4];
        }
        #pragma unroll
        for (int nt = 0; nt < 8; nt++) {
            const int nc = warpN + nt*8 + gid;
            unsigned bh0 = WhiP[(kk0 + tig    )*WST2 + nc];
            unsigned bh1 = WhiP[(kk0 + tig + 4)*WST2 + nc];
            unsigned bl0 = WloP[(kk0 + tig    )*WST2 + nc];
            unsigned bl1 = WloP[(kk0 + tig + 4)*WST2 + nc];
            #pragma unroll
            for (int mt = 0; mt < 2; mt++) {
                mma_bf16(acc[mt][nt], ahi[mt], bh0, bh1);
                mma_bf16(acc[mt][nt], alo[mt], bh0, bh1);
                mma_bf16(acc[mt][nt], ahi[mt], bl0, bl1);
            }
        }
    }

    // ---- direct-from-fragment epilogue (bias + scatter/residual) ----
    #pragma unroll
    for (int mt = 0; mt < 2; mt++) {
        const int rlA = warpM + mt*16 + gid;
        const int rlB = rlA + 8;
        #pragma unroll
        for (int half = 0; half < 2; half++) {
            const int rl = half ? rlB : rlA;
            const int gm = m0 + rl;
            float* orow;
            const float* rrow = 0;
            if (mode == 0)      orow = g_qf + (size_t)((gm & 3)*NPTS + (gm >> 2)) * DD;
            else if (mode == 1) orow = g_kf + (size_t)((gm & 3)*NPTS + (gm >> 2)) * DD;
            else if (mode == 2) orow = g_vf + (size_t)((gm & 3)*NPTS + (gm >> 2)) * DD;
            else if (mode == 3) { orow = outext + (size_t)gm * DD; rrow = resid + (size_t)gm * DD; }
            else if (mode == 4) orow = g_pe + (size_t)gm * DD;
            else                orow = g_h  + (size_t)gm * DD;
            #pragma unroll
            for (int nt = 0; nt < 8; nt++) {
                const int col = warpN + nt*8 + 2*tig;
                float2 v;
                v.x = acc[mt][nt][half*2    ] + sb[col];
                v.y = acc[mt][nt][half*2 + 1] + sb[col + 1];
                if (mode == 3) {
                    float2 rr = *(const float2*)(rrow + col);
                    v.x += rr.x; v.y += rr.y;
                }
                *(float2*)(orow + col) = v;
            }
        }
    }
}

// ============================================================================
// build h: row r=(g,k) of [NR,128]: h = gelu(rel . Wp1[:,d] + bp1[d])
// (round-3 verbatim — verified passing)
// ============================================================================
__global__ __launch_bounds__(256, 1) void buildh_k(
    const float* __restrict__ pos,
    const float* __restrict__ Wp1, const float* __restrict__ bp1)
{
    const int gid = blockIdx.x * 256 + threadIdx.x;
    const int r = gid >> 7, d = gid & 127;
    const int g = r >> 3;
    const int b = g >> 13, n = g & (NPTS - 1);
    const int id = g_idx[r];
    const float* pb = pos + (size_t)b * NPTS * 3;
    const float rx = pb[n*3+0] - pb[id*3+0];
    const float ry = pb[n*3+1] - pb[id*3+1];
    const float rz = pb[n*3+2] - pb[id*3+2];
    float z = fmaf(rz, Wp1[256+d], fmaf(ry, Wp1[128+d], fmaf(rx, Wp1[d], bp1[d])));
    g_h[gid] = 0.5f * z * (1.f + erff(z * 0.70710678118654752f));
}

// ============================================================================
// build u: u[r][d] = q[g][d] - kf[idx[r]][d] + pe[r][d]  (round-3 verbatim)
// ============================================================================
__global__ __launch_bounds__(256, 1) void buildu_k()
{
    const int gid = blockIdx.x * 256 + threadIdx.x;
    const int r = gid >> 7, d = gid & 127;
    const int g = r >> 3;
    const int id = g_idx[r];
    const int b = g >> 13;
    float qv = g_qf[(size_t)g * DD + d];
    float kv = g_kf[((size_t)b * NPTS + id) * DD + d];
    g_u[gid] = qv - kv + g_pe[gid];
}

// ============================================================================
// finish: per (g,k) row softmax over d of a (= g_h after mode-5 GEMM),
// res[g][d] = sum_k sm * (v_gather + pe)   (round-3 verbatim)
// ============================================================================
__global__ __launch_bounds__(256, 1) void finish_k()
{
    __shared__ float rA[2][32];
    __shared__ float rB[2][32];

    const int tid  = threadIdx.x;
    const int grp  = tid >> 7;
    const int d    = tid & 127;
    const int lane = tid & 31;
    const int wsub = (tid >> 5) & 3;
    const int g    = blockIdx.x * 2 + grp;
    const int b    = g >> 13;
    const float scale = 0.08838834764831845f;   // 1/sqrt(128)

    float a[8];
    #pragma unroll
    for (int k = 0; k < 8; ++k)
        a[k] = g_h[((size_t)g*8 + k) * DD + d] * scale;

    float red[8];
    #pragma unroll
    for (int k = 0; k < 8; ++k) red[k] = a[k];
    #pragma unroll
    for (int off = 16; off > 0; off >>= 1)
        #pragma unroll
        for (int k = 0; k < 8; ++k)
            red[k] = fmaxf(red[k], __shfl_xor_sync(0xffffffffu, red[k], off));
    if (lane == 0) {
        #pragma unroll
        for (int k = 0; k < 8; ++k) rA[grp][wsub*8 + k] = red[k];
    }
    __syncthreads();

    float e[8];
    #pragma unroll
    for (int k = 0; k < 8; ++k) {
        float bm = fmaxf(fmaxf(rA[grp][k], rA[grp][8+k]),
                         fmaxf(rA[grp][16+k], rA[grp][24+k]));
        e[k] = __expf(a[k] - bm);
        red[k] = e[k];
    }
    #pragma unroll
    for (int off = 16; off > 0; off >>= 1)
        #pragma unroll
        for (int k = 0; k < 8; ++k)
            red[k] += __shfl_xor_sync(0xffffffffu, red[k], off);
    if (lane == 0) {
        #pragma unroll
        for (int k = 0; k < 8; ++k) rB[grp][wsub*8 + k] = red[k];
    }
    __syncthreads();

    float rsum = 0.f;
    #pragma unroll
    for (int k = 0; k < 8; ++k) {
        float tot = (rB[grp][k] + rB[grp][8+k]) + (rB[grp][16+k] + rB[grp][24+k]);
        float smx = e[k] / tot;
        int id = g_idx[(size_t)g*8 + k];
        float v  = g_vf[((size_t)b * NPTS + id) * DD + d];
        float pe = g_pe[((size_t)g*8 + k) * DD + d];
        rsum = fmaf(smx, v + pe, rsum);
    }
    g_res[(size_t)g * DD + d] = rsum;
}

// ============================================================================
// KNN (4-way split, conflict-free tiles) — round-3 verbatim
// ============================================================================
__global__ __launch_bounds__(256, 1) void knn_k(const float* __restrict__ pos)
{
    __shared__ float4 cand[1028];
    __shared__ float  sd[256*8];
    __shared__ int    si[256*8];

    const int b = blockIdx.y;
    const int t = threadIdx.x;
    const int q = blockIdx.x * 64 + (t >> 2);
    const int s = t & 3;
    const float* pb = pos + (size_t)b * NPTS * 3;

    const float qx = pb[q*3], qy = pb[q*3+1], qz = pb[q*3+2];
    const float qsq = fmaf(qz, qz, fmaf(qy, qy, qx*qx));

    float bd[8]; int bi[8];
    #pragma unroll
    for (int k = 0; k < 8; k++) { bd[k] = 1e30f; bi[k] = 0x7fffffff; }

    const int base = s * 257;
    for (int t0 = 0; t0 < NPTS; t0 += 1024) {
        __syncthreads();
        #pragma unroll
        for (int i = t; i < 1024; i += 256) {
            float x = pb[(t0+i)*3], y = pb[(t0+i)*3+1], z = pb[(t0+i)*3+2];
            cand[i + (i >> 8)] = make_float4(x, y, z, fmaf(z, z, fmaf(y, y, x*x)));
        }
        __syncthreads();
        #pragma unroll 4
        for (int m = 0; m < 256; ++m) {
            float4 c = cand[base + m];
            float dot = fmaf(qz, c.z, fmaf(qy, c.y, qx * c.x));
            float d2  = fmaf(-2.f, dot, qsq + c.w);
            if (d2 < bd[7]) {
                bd[7] = d2; bi[7] = t0 + s*256 + m;
                #pragma unroll
                for (int r = 7; r > 0; --r) {
                    if (bd[r] < bd[r-1]) {
                        float td = bd[r]; bd[r] = bd[r-1]; bd[r-1] = td;
                        int   ti = bi[r]; bi[r] = bi[r-1]; bi[r-1] = ti;
                    }
                }
            }
        }
    }

    #pragma unroll
    for (int k = 0; k < 8; k++) { sd[t*8+k] = bd[k]; si[t*8+k] = bi[k]; }
    __syncthreads();

    if (s == 0) {
        int p[4] = {0, 0, 0, 0};
        int* op = g_idx + ((size_t)b * NPTS + q) * KK;
        #pragma unroll
        for (int o = 0; o < 8; ++o) {
            float bdv = 1e38f; int biv = 0x7fffffff; int bl = 0;
            #pragma unroll
            for (int l = 0; l < 4; ++l) {
                float dv = sd[(t+l)*8 + p[l]];
                int   iv = si[(t+l)*8 + p[l]];
                if (dv < bdv || (dv == bdv && iv < biv)) { bdv = dv; biv = iv; bl = l; }
            }
            op[o] = biv;
            p[bl]++;
        }
    }
}

// ============================================================================
// host launch
// ============================================================================
extern "C" void kernel_launch(void* const* d_in, const int* in_sizes, int n_in,
                              void* d_out, int out_size)
{
    const float* query = (const float*)d_in[0];
    const float* pos   = (const float*)d_in[1];
    const float* Wq  = (const float*)d_in[2];  const float* bq  = (const float*)d_in[3];
    const float* Wk  = (const float*)d_in[4];  const float* bk  = (const float*)d_in[5];
    const float* Wv  = (const float*)d_in[6];  const float* bv  = (const float*)d_in[7];
    const float* Wp1 = (const float*)d_in[8];  const float* bp1 = (const float*)d_in[9];
    const float* Wp2 = (const float*)d_in[10]; const float* bp2 = (const float*)d_in[11];
    const float* Wg  = (const float*)d_in[12]; const float* bg  = (const float*)d_in[13];
    const float* Wo  = (const float*)d_in[14]; const float* bo  = (const float*)d_in[15];
    float* out = (float*)d_out;

    cudaFuncSetAttribute(gemm_mma, cudaFuncAttributeMaxDynamicSharedMemorySize, SMEM_BYTES);

    // QKV projections -> g_qf/g_kf/g_vf in [B,N,D]
    gemm_mma<<<NB/128, 256, SMEM_BYTES>>>(query, Wq, bq, 0, 0, 0);
    gemm_mma<<<NB/128, 256, SMEM_BYTES>>>(query, Wk, bk, 0, 0, 1);
    gemm_mma<<<NB/128, 256, SMEM_BYTES>>>(query, Wv, bv, 0, 0, 2);

    // KNN
    knn_k<<<dim3(NPTS/64, BB), 256>>>(pos);

    // h = gelu(lin1(rel))          [NR,128]
    buildh_k<<<NR*DD/256, 256>>>(pos, Wp1, bp1);

    // pe = h @ Wp2 + bp2           [NR,128]
    gemm_mma<<<NR/128, 256, SMEM_BYTES>>>(0, Wp2, bp2, 0, 0, 4);

    // u = q - k_knn + pe           [NR,128]
    buildu_k<<<NR*DD/256, 256>>>();

    // a = u @ Wg + bg              [NR,128]  (into g_h)
    gemm_mma<<<NR/128, 256, SMEM_BYTES>>>(0, Wg, bg, 0, 0, 5);

    // softmax over d + weighted sum over k -> g_res [B,N,D]
    finish_k<<<NB/2, 256>>>();

    // out = res@Wo + bo + query    [N,B,D]
    gemm_mma<<<NB/128, 256, SMEM_BYTES>>>(query, Wo, bo, query, out, 3);
}

// round 9
// speedup vs baseline: 1.8165x; 1.0847x over previous
#include <cuda_runtime.h>
#include <math.h>

#define NPTS 8192
#define BB   4
#define DD   128
#define KK   8
#define NB   (NPTS*BB)        // 32768
#define NR   (NB*KK)          // 262144

#define WST2 136              // W hi/lo tile word stride (rows = 64 k-pairs)
#define AST2 68               // A hi/lo tile word stride (rows = 128 m)

// smem word offsets
#define OFF_WHI 0             // 64*136  = 8704
#define OFF_WLO 8704
#define OFF_AHI 17408         // 128*68  = 8704
#define OFF_ALO 26112
#define OFF_SB  34816         // bias[128]
#define SMEM_WORDS 34944
#define SMEM_BYTES (SMEM_WORDS*4)   // 139776

// ---------------- scratch ----------------
__device__ float g_qf[BB*NPTS*DD];
__device__ float g_kf[BB*NPTS*DD];
__device__ float g_vf[BB*NPTS*DD];
__device__ float g_res[BB*NPTS*DD];
__device__ int   g_idx[BB*NPTS*KK];
__device__ float g_h [NR*DD];        // h = gelu(lin1(rel)); later reused for logits a
__device__ float g_pe[NR*DD];
__device__ float g_u [NR*DD];

// ---------------- bf16 helpers ----------------
__device__ __forceinline__ unsigned bfpack(float lo_elem, float hi_elem) {
    unsigned r;
    asm("cvt.rn.bf16x2.f32 %0, %1, %2;" : "=r"(r) : "f"(hi_elem), "f"(lo_elem));
    return r;
}
__device__ __forceinline__ void bfsplit(float x0, float x1,
                                        unsigned& hp, unsigned& lp) {
    hp = bfpack(x0, x1);
    float h0 = __uint_as_float(hp << 16);
    float h1 = __uint_as_float(hp & 0xFFFF0000u);
    lp = bfpack(x0 - h0, x1 - h1);
}
__device__ __forceinline__ void mma_bf16(float* c, const unsigned* a,
                                         unsigned b0, unsigned b1) {
    asm volatile(
        "mma.sync.aligned.m16n8k16.row.col.f32.bf16.bf16.f32 "
        "{%0,%1,%2,%3}, {%4,%5,%6,%7}, {%8,%9}, {%0,%1,%2,%3};"
        : "+f"(c[0]), "+f"(c[1]), "+f"(c[2]), "+f"(c[3])
        : "r"(a[0]), "r"(a[1]), "r"(a[2]), "r"(a[3]), "r"(b0), "r"(b1));
}

// ============================================================================
// bf16-split MMA GEMM (verified round-8 engine — unchanged).
// Modes:
//  0/1/2: A=query rows (n*B+b), out scattered to g_qf/g_kf/g_vf [B,N,D]
//  3:     A=g_res (permuted rows), out -> d_out [N,B,D] + query residual
//  4:     A=g_h  plain rows, out -> g_pe
//  5:     A=g_u  plain rows, out -> g_h
// ============================================================================
__global__ __launch_bounds__(256, 1) void gemm_mma(
    const float* __restrict__ Aext, const float* __restrict__ W,
    const float* __restrict__ bias, const float* __restrict__ resid,
    float* __restrict__ outext, int mode)
{
    extern __shared__ unsigned smw[];
    unsigned* WhiP = smw + OFF_WHI;
    unsigned* WloP = smw + OFF_WLO;
    unsigned* AhiP = smw + OFF_AHI;
    unsigned* AloP = smw + OFF_ALO;
    float* sb = (float*)(smw + OFF_SB);

    const int tid = threadIdx.x;
    const int m0  = blockIdx.x * 128;

    #pragma unroll
    for (int p = tid; p < 2048; p += 256) {
        int kk = p >> 5, nq = p & 31;
        const float4 L0 = *(const float4*)(W + (2*kk    )*128 + 4*nq);
        const float4 L1 = *(const float4*)(W + (2*kk + 1)*128 + 4*nq);
        uint4 h, l;
        bfsplit(L0.x, L1.x, h.x, l.x);
        bfsplit(L0.y, L1.y, h.y, l.y);
        bfsplit(L0.z, L1.z, h.z, l.z);
        bfsplit(L0.w, L1.w, h.w, l.w);
        *(uint4*)(WhiP + kk*WST2 + 4*nq) = h;
        *(uint4*)(WloP + kk*WST2 + 4*nq) = l;
    }
    if (tid < 128) sb[tid] = bias[tid];

    {
        const float* Aptr = (mode == 3) ? (const float*)g_res :
                            (mode == 4) ? (const float*)g_h  :
                            (mode == 5) ? (const float*)g_u  : Aext;
        #pragma unroll
        for (int i = tid; i < 4096; i += 256) {
            int m = i >> 5, cc = i & 31;
            int gm = m0 + m;
            int arow = (mode == 3) ? ((gm & 3) * NPTS + (gm >> 2)) : gm;
            float4 v = *(const float4*)(Aptr + (size_t)arow*DD + cc*4);
            uint2 h, l;
            bfsplit(v.x, v.y, h.x, l.x);
            bfsplit(v.z, v.w, h.y, l.y);
            *(uint2*)(AhiP + m*AST2 + 2*cc) = h;
            *(uint2*)(AloP + m*AST2 + 2*cc) = l;
        }
    }
    __syncthreads();

    const int lane  = tid & 31;
    const int wid   = tid >> 5;
    const int warpM = (wid & 3) * 32;
    const int warpN = (wid >> 2) * 64;
    const int gid   = lane >> 2;
    const int tig   = lane & 3;

    float acc[2][8][4];
    #pragma unroll
    for (int mt = 0; mt < 2; mt++)
        #pragma unroll
        for (int nt = 0; nt < 8; nt++)
            #pragma unroll
            for (int q = 0; q < 4; q++) acc[mt][nt][q] = 0.f;

    #pragma unroll 1
    for (int ks = 0; ks < 8; ++ks) {
        const int kk0 = ks * 8;
        unsigned ahi[2][4], alo[2][4];
        #pragma unroll
        for (int mt = 0; mt < 2; mt++) {
            const int r0 = warpM + mt*16 + gid;
            ahi[mt][0] = AhiP[(r0    )*AST2 + kk0 + tig];
            ahi[mt][1] = AhiP[(r0 + 8)*AST2 + kk0 + tig];
            ahi[mt][2] = AhiP[(r0    )*AST2 + kk0 + tig + 4];
            ahi[mt][3] = AhiP[(r0 + 8)*AST2 + kk0 + tig + 4];
            alo[mt][0] = AloP[(r0    )*AST2 + kk0 + tig];
            alo[mt][1] = AloP[(r0 + 8)*AST2 + kk0 + tig];
            alo[mt][2] = AloP[(r0    )*AST2 + kk0 + tig + 4];
            alo[mt][3] = AloP[(r0 + 8)*AST2 + kk0 + tig + 4];
        }
        #pragma unroll
        for (int nt = 0; nt < 8; nt++) {
            const int nc = warpN + nt*8 + gid;
            unsigned bh0 = WhiP[(kk0 + tig    )*WST2 + nc];
            unsigned bh1 = WhiP[(kk0 + tig + 4)*WST2 + nc];
            unsigned bl0 = WloP[(kk0 + tig    )*WST2 + nc];
            unsigned bl1 = WloP[(kk0 + tig + 4)*WST2 + nc];
            #pragma unroll
            for (int mt = 0; mt < 2; mt++) {
                mma_bf16(acc[mt][nt], ahi[mt], bh0, bh1);
                mma_bf16(acc[mt][nt], alo[mt], bh0, bh1);
                mma_bf16(acc[mt][nt], ahi[mt], bl0, bl1);
            }
        }
    }

    #pragma unroll
    for (int mt = 0; mt < 2; mt++) {
        const int rlA = warpM + mt*16 + gid;
        const int rlB = rlA + 8;
        #pragma unroll
        for (int half = 0; half < 2; half++) {
            const int rl = half ? rlB : rlA;
            const int gm = m0 + rl;
            float* orow;
            const float* rrow = 0;
            if (mode == 0)      orow = g_qf + (size_t)((gm & 3)*NPTS + (gm >> 2)) * DD;
            else if (mode == 1) orow = g_kf + (size_t)((gm & 3)*NPTS + (gm >> 2)) * DD;
            else if (mode == 2) orow = g_vf + (size_t)((gm & 3)*NPTS + (gm >> 2)) * DD;
            else if (mode == 3) { orow = outext + (size_t)gm * DD; rrow = resid + (size_t)gm * DD; }
            else if (mode == 4) orow = g_pe + (size_t)gm * DD;
            else                orow = g_h  + (size_t)gm * DD;
            #pragma unroll
            for (int nt = 0; nt < 8; nt++) {
                const int col = warpN + nt*8 + 2*tig;
                float2 v;
                v.x = acc[mt][nt][half*2    ] + sb[col];
                v.y = acc[mt][nt][half*2 + 1] + sb[col + 1];
                if (mode == 3) {
                    float2 rr = *(const float2*)(rrow + col);
                    v.x += rr.x; v.y += rr.y;
                }
                *(float2*)(orow + col) = v;
            }
        }
    }
}

// ============================================================================
// KNN v3: 8-way candidate split per query (32 queries x 8 splits per block),
// shift trick (compare s = -2*dot + |c|^2; d2 = qsq + s, qsq const per query),
// bank-conflict-free chunk bases (stride 129 float4s).
// ============================================================================
__global__ __launch_bounds__(256, 1) void knn_k(const float* __restrict__ pos)
{
    __shared__ float4 cand[1032];        // 8 chunks of 129 (128 used)
    __shared__ float  sd[256*8];
    __shared__ int    si[256*8];

    const int b = blockIdx.y;
    const int t = threadIdx.x;
    const int q = blockIdx.x * 32 + (t >> 3);
    const int s = t & 7;
    const float* pb = pos + (size_t)b * NPTS * 3;

    const float qx = pb[q*3], qy = pb[q*3+1], qz = pb[q*3+2];
    const float nx = -2.f*qx, ny = -2.f*qy, nz = -2.f*qz;

    float bd[8]; int bi[8];
    #pragma unroll
    for (int k = 0; k < 8; k++) { bd[k] = 1e30f; bi[k] = 0x7fffffff; }

    const int base = s * 129;
    for (int t0 = 0; t0 < NPTS; t0 += 1024) {
        __syncthreads();
        #pragma unroll
        for (int i = t; i < 1024; i += 256) {
            float x = pb[(t0+i)*3], y = pb[(t0+i)*3+1], z = pb[(t0+i)*3+2];
            cand[i + (i >> 7)] = make_float4(x, y, z, fmaf(z, z, fmaf(y, y, x*x)));
        }
        __syncthreads();
        #pragma unroll 8
        for (int m = 0; m < 128; ++m) {
            float4 c = cand[base + m];
            float sv = fmaf(nx, c.x, fmaf(ny, c.y, fmaf(nz, c.z, c.w)));
            if (sv < bd[7]) {
                bd[7] = sv; bi[7] = t0 + s*128 + m;
                #pragma unroll
                for (int r = 7; r > 0; --r) {
                    if (bd[r] < bd[r-1]) {
                        float td = bd[r]; bd[r] = bd[r-1]; bd[r-1] = td;
                        int   ti = bi[r]; bi[r] = bi[r-1]; bi[r-1] = ti;
                    }
                }
            }
        }
    }

    #pragma unroll
    for (int k = 0; k < 8; k++) { sd[t*8+k] = bd[k]; si[t*8+k] = bi[k]; }
    __syncthreads();

    if (s == 0) {
        int p[8] = {0,0,0,0,0,0,0,0};
        int* op = g_idx + ((size_t)b * NPTS + q) * KK;
        #pragma unroll
        for (int o = 0; o < 8; ++o) {
            float bdv = 1e38f; int biv = 0x7fffffff; int bl = 0;
            #pragma unroll
            for (int l = 0; l < 8; ++l) {
                float dv = sd[(t+l)*8 + p[l]];
                int   iv = si[(t+l)*8 + p[l]];
                if (dv < bdv || (dv == bdv && iv < biv)) { bdv = dv; biv = iv; bl = l; }
            }
            op[o] = biv;
            p[bl]++;
        }
    }
}

// ============================================================================
// build h (float4): thread -> 4 consecutive d of one row r=(g,k).
// ============================================================================
__global__ __launch_bounds__(256, 1) void buildh_k(
    const float* __restrict__ pos,
    const float* __restrict__ Wp1, const float* __restrict__ bp1)
{
    const int gid = blockIdx.x * 256 + threadIdx.x;   // < NR*32
    const int r = gid >> 5, d0 = (gid & 31) * 4;
    const int g = r >> 3;
    const int b = g >> 13, n = g & (NPTS - 1);
    const int id = g_idx[r];
    const float* pb = pos + (size_t)b * NPTS * 3;
    const float rx = pb[n*3+0] - pb[id*3+0];
    const float ry = pb[n*3+1] - pb[id*3+1];
    const float rz = pb[n*3+2] - pb[id*3+2];
    const float4 wx = *(const float4*)(Wp1 + d0);
    const float4 wy = *(const float4*)(Wp1 + 128 + d0);
    const float4 wz = *(const float4*)(Wp1 + 256 + d0);
    const float4 bb = *(const float4*)(bp1 + d0);
    float4 o;
    {
        float z = fmaf(rz, wx.x*0.f + wz.x, fmaf(ry, wy.x, fmaf(rx, wx.x, bb.x)));
        o.x = 0.5f * z * (1.f + erff(z * 0.70710678118654752f));
    }
    {
        float z = fmaf(rz, wz.y, fmaf(ry, wy.y, fmaf(rx, wx.y, bb.y)));
        o.y = 0.5f * z * (1.f + erff(z * 0.70710678118654752f));
    }
    {
        float z = fmaf(rz, wz.z, fmaf(ry, wy.z, fmaf(rx, wx.z, bb.z)));
        o.z = 0.5f * z * (1.f + erff(z * 0.70710678118654752f));
    }
    {
        float z = fmaf(rz, wz.w, fmaf(ry, wy.w, fmaf(rx, wx.w, bb.w)));
        o.w = 0.5f * z * (1.f + erff(z * 0.70710678118654752f));
    }
    // fix first lane (wrote wx.x*0+wz.x to keep compiler from reordering; recompute cleanly)
    {
        float z = fmaf(rz, wz.x, fmaf(ry, wy.x, fmaf(rx, wx.x, bb.x)));
        o.x = 0.5f * z * (1.f + erff(z * 0.70710678118654752f));
    }
    *(float4*)(g_h + (size_t)r*DD + d0) = o;
}

// ============================================================================
// build u (float4): u[r][seg] = q[g][seg] - kf[idx[r]][seg] + pe[r][seg]
// ============================================================================
__global__ __launch_bounds__(256, 1) void buildu_k()
{
    const int gid = blockIdx.x * 256 + threadIdx.x;   // < NR*32
    const int r = gid >> 5, seg = (gid & 31) * 4;
    const int g = r >> 3;
    const int id = g_idx[r];
    const int b = g >> 13;
    float4 qv = *(const float4*)(g_qf + (size_t)g * DD + seg);
    float4 kv = *(const float4*)(g_kf + ((size_t)b * NPTS + id) * DD + seg);
    float4 pe = *(const float4*)(g_pe + (size_t)r * DD + seg);
    float4 u;
    u.x = qv.x - kv.x + pe.x; u.y = qv.y - kv.y + pe.y;
    u.z = qv.z - kv.z + pe.z; u.w = qv.w - kv.w + pe.w;
    *(float4*)(g_u + (size_t)r * DD + seg) = u;
}

// ============================================================================
// finish: per (g,k) row softmax over d of a (= g_h), res = sum_k sm*(v+pe)
// ============================================================================
__global__ __launch_bounds__(256, 1) void finish_k()
{
    __shared__ float rA[2][32];
    __shared__ float rB[2][32];

    const int tid  = threadIdx.x;
    const int grp  = tid >> 7;
    const int d    = tid & 127;
    const int lane = tid & 31;
    const int wsub = (tid >> 5) & 3;
    const int g    = blockIdx.x * 2 + grp;
    const int b    = g >> 13;
    const float scale = 0.08838834764831845f;   // 1/sqrt(128)

    float a[8];
    #pragma unroll
    for (int k = 0; k < 8; ++k)
        a[k] = g_h[((size_t)g*8 + k) * DD + d] * scale;

    float red[8];
    #pragma unroll
    for (int k = 0; k < 8; ++k) red[k] = a[k];
    #pragma unroll
    for (int off = 16; off > 0; off >>= 1)
        #pragma unroll
        for (int k = 0; k < 8; ++k)
            red[k] = fmaxf(red[k], __shfl_xor_sync(0xffffffffu, red[k], off));
    if (lane == 0) {
        #pragma unroll
        for (int k = 0; k < 8; ++k) rA[grp][wsub*8 + k] = red[k];
    }
    __syncthreads();

    float e[8];
    #pragma unroll
    for (int k = 0; k < 8; ++k) {
        float bm = fmaxf(fmaxf(rA[grp][k], rA[grp][8+k]),
                         fmaxf(rA[grp][16+k], rA[grp][24+k]));
        e[k] = __expf(a[k] - bm);
        red[k] = e[k];
    }
    #pragma unroll
    for (int off = 16; off > 0; off >>= 1)
        #pragma unroll
        for (int k = 0; k < 8; ++k)
            red[k] += __shfl_xor_sync(0xffffffffu, red[k], off);
    if (lane == 0) {
        #pragma unroll
        for (int k = 0; k < 8; ++k) rB[grp][wsub*8 + k] = red[k];
    }
    __syncthreads();

    float rsum = 0.f;
    #pragma unroll
    for (int k = 0; k < 8; ++k) {
        float tot = (rB[grp][k] + rB[grp][8+k]) + (rB[grp][16+k] + rB[grp][24+k]);
        float smx = e[k] / tot;
        int id = g_idx[(size_t)g*8 + k];
        float v  = g_vf[((size_t)b * NPTS + id) * DD + d];
        float pe = g_pe[((size_t)g*8 + k) * DD + d];
        rsum = fmaf(smx, v + pe, rsum);
    }
    g_res[(size_t)g * DD + d] = rsum;
}

// ============================================================================
// host launch
// ============================================================================
extern "C" void kernel_launch(void* const* d_in, const int* in_sizes, int n_in,
                              void* d_out, int out_size)
{
    const float* query = (const float*)d_in[0];
    const float* pos   = (const float*)d_in[1];
    const float* Wq  = (const float*)d_in[2];  const float* bq  = (const float*)d_in[3];
    const float* Wk  = (const float*)d_in[4];  const float* bk  = (const float*)d_in[5];
    const float* Wv  = (const float*)d_in[6];  const float* bv  = (const float*)d_in[7];
    const float* Wp1 = (const float*)d_in[8];  const float* bp1 = (const float*)d_in[9];
    const float* Wp2 = (const float*)d_in[10]; const float* bp2 = (const float*)d_in[11];
    const float* Wg  = (const float*)d_in[12]; const float* bg  = (const float*)d_in[13];
    const float* Wo  = (const float*)d_in[14]; const float* bo  = (const float*)d_in[15];
    float* out = (float*)d_out;

    cudaFuncSetAttribute(gemm_mma, cudaFuncAttributeMaxDynamicSharedMemorySize, SMEM_BYTES);

    // KNN first (longest independent kernel)
    knn_k<<<dim3(NPTS/32, BB), 256>>>(pos);

    // QKV projections -> g_qf/g_kf/g_vf in [B,N,D]
    gemm_mma<<<NB/128, 256, SMEM_BYTES>>>(query, Wq, bq, 0, 0, 0);
    gemm_mma<<<NB/128, 256, SMEM_BYTES>>>(query, Wk, bk, 0, 0, 1);
    gemm_mma<<<NB/128, 256, SMEM_BYTES>>>(query, Wv, bv, 0, 0, 2);

    // h = gelu(lin1(rel))          [NR,128]
    buildh_k<<<NR*32/256, 256>>>(pos, Wp1, bp1);

    // pe = h @ Wp2 + bp2           [NR,128]
    gemm_mma<<<NR/128, 256, SMEM_BYTES>>>(0, Wp2, bp2, 0, 0, 4);

    // u = q - k_knn + pe           [NR,128]
    buildu_k<<<NR*32/256, 256>>>();

    // a = u @ Wg + bg              [NR,128]  (into g_h)
    gemm_mma<<<NR/128, 256, SMEM_BYTES>>>(0, Wg, bg, 0, 0, 5);

    // softmax over d + weighted sum over k -> g_res [B,N,D]
    finish_k<<<NB/2, 256>>>();

    // out = res@Wo + bo + query    [N,B,D]
    gemm_mma<<<NB/128, 256, SMEM_BYTES>>>(query, Wo, bo, query, out, 3);
}

// round 10
// speedup vs baseline: 1.8758x; 1.0327x over previous
#include <cuda_runtime.h>
#include <math.h>

#define NPTS 8192
#define BB   4
#define DD   128
#define KK   8
#define NB   (NPTS*BB)        // 32768
#define NR   (NB*KK)          // 262144

#define THREADS 512

#define WST2 136              // W hi/lo tile word stride (rows = 64 k-pairs)
#define AST2 68               // A hi/lo tile word stride (rows = 128 m)

// smem word offsets
#define OFF_WHI 0             // 64*136  = 8704
#define OFF_WLO 8704
#define OFF_AHI 17408         // 128*68  = 8704
#define OFF_ALO 26112
#define OFF_SB  34816         // bias[128]
#define SMEM_WORDS 34944
#define SMEM_BYTES (SMEM_WORDS*4)   // 139776

// ---------------- scratch ----------------
__device__ float g_qf[BB*NPTS*DD];
__device__ float g_kf[BB*NPTS*DD];
__device__ float g_vf[BB*NPTS*DD];
__device__ float g_res[BB*NPTS*DD];
__device__ int   g_idx[BB*NPTS*KK];
__device__ float g_h [NR*DD];        // h = gelu(lin1(rel)); later reused for logits a
__device__ float g_pe[NR*DD];
__device__ float g_u [NR*DD];

// ---------------- bf16 helpers ----------------
__device__ __forceinline__ unsigned bfpack(float lo_elem, float hi_elem) {
    unsigned r;
    asm("cvt.rn.bf16x2.f32 %0, %1, %2;" : "=r"(r) : "f"(hi_elem), "f"(lo_elem));
    return r;
}
__device__ __forceinline__ void bfsplit(float x0, float x1,
                                        unsigned& hp, unsigned& lp) {
    hp = bfpack(x0, x1);
    float h0 = __uint_as_float(hp << 16);
    float h1 = __uint_as_float(hp & 0xFFFF0000u);
    lp = bfpack(x0 - h0, x1 - h1);
}
__device__ __forceinline__ void mma_bf16(float* c, const unsigned* a,
                                         unsigned b0, unsigned b1) {
    asm volatile(
        "mma.sync.aligned.m16n8k16.row.col.f32.bf16.bf16.f32 "
        "{%0,%1,%2,%3}, {%4,%5,%6,%7}, {%8,%9}, {%0,%1,%2,%3};"
        : "+f"(c[0]), "+f"(c[1]), "+f"(c[2]), "+f"(c[3])
        : "r"(a[0]), "r"(a[1]), "r"(a[2]), "r"(a[3]), "r"(b0), "r"(b1));
}

// ============================================================================
// bf16-split MMA GEMM, persistent tile loop, 512 threads (16 warps, 4x4 grid).
// W is loaded+split ONCE per block; blocks grid-stride over 128-row A tiles.
// D = Ahi*Whi + Alo*Whi + Ahi*Wlo  (fp32 accumulate) — same math/order as R8.
// Modes:
//  0/1/2: A=query rows (n*B+b), out scattered to g_qf/g_kf/g_vf [B,N,D]
//  3:     A=g_res (permuted rows), out -> d_out [N,B,D] + query residual
//  4:     A=g_h  plain rows, out -> g_pe
//  5:     A=g_u  plain rows, out -> g_h
// ============================================================================
__global__ __launch_bounds__(THREADS, 1) void gemm_mma(
    const float* __restrict__ Aext, const float* __restrict__ W,
    const float* __restrict__ bias, const float* __restrict__ resid,
    float* __restrict__ outext, int ntiles, int mode)
{
    extern __shared__ unsigned smw[];
    unsigned* WhiP = smw + OFF_WHI;
    unsigned* WloP = smw + OFF_WLO;
    unsigned* AhiP = smw + OFF_AHI;
    unsigned* AloP = smw + OFF_ALO;
    float* sb = (float*)(smw + OFF_SB);

    const int tid = threadIdx.x;

    // ---- W -> WhiP/WloP + bias: ONCE per block ----
    #pragma unroll
    for (int p = tid; p < 2048; p += THREADS) {
        int kk = p >> 5, nq = p & 31;
        const float4 L0 = *(const float4*)(W + (2*kk    )*128 + 4*nq);
        const float4 L1 = *(const float4*)(W + (2*kk + 1)*128 + 4*nq);
        uint4 h, l;
        bfsplit(L0.x, L1.x, h.x, l.x);
        bfsplit(L0.y, L1.y, h.y, l.y);
        bfsplit(L0.z, L1.z, h.z, l.z);
        bfsplit(L0.w, L1.w, h.w, l.w);
        *(uint4*)(WhiP + kk*WST2 + 4*nq) = h;
        *(uint4*)(WloP + kk*WST2 + 4*nq) = l;
    }
    if (tid < 128) sb[tid] = bias[tid];

    const float* Aptr = (mode == 3) ? (const float*)g_res :
                        (mode == 4) ? (const float*)g_h  :
                        (mode == 5) ? (const float*)g_u  : Aext;

    const int lane  = tid & 31;
    const int wid   = tid >> 5;
    const int warpM = (wid & 3) * 32;
    const int warpN = (wid >> 2) * 32;
    const int gid   = lane >> 2;
    const int tig   = lane & 3;

    for (int tile = blockIdx.x; tile < ntiles; tile += gridDim.x) {
        const int m0 = tile * 128;

        // ---- A tile -> AhiP/AloP ----
        __syncthreads();   // prior iteration's readers done before overwrite
        #pragma unroll
        for (int i = tid; i < 4096; i += THREADS) {
            int m = i >> 5, cc = i & 31;
            int gm = m0 + m;
            int arow = (mode == 3) ? ((gm & 3) * NPTS + (gm >> 2)) : gm;
            float4 v = *(const float4*)(Aptr + (size_t)arow*DD + cc*4);
            uint2 h, l;
            bfsplit(v.x, v.y, h.x, l.x);
            bfsplit(v.z, v.w, h.y, l.y);
            *(uint2*)(AhiP + m*AST2 + 2*cc) = h;
            *(uint2*)(AloP + m*AST2 + 2*cc) = l;
        }
        __syncthreads();

        // ---- MMA mainloop: per warp M=32 (2 mt), N=32 (4 nt) ----
        float acc[2][4][4];
        #pragma unroll
        for (int mt = 0; mt < 2; mt++)
            #pragma unroll
            for (int nt = 0; nt < 4; nt++)
                #pragma unroll
                for (int q = 0; q < 4; q++) acc[mt][nt][q] = 0.f;

        #pragma unroll 1
        for (int ks = 0; ks < 8; ++ks) {
            const int kk0 = ks * 8;
            unsigned ahi[2][4], alo[2][4];
            #pragma unroll
            for (int mt = 0; mt < 2; mt++) {
                const int r0 = warpM + mt*16 + gid;
                ahi[mt][0] = AhiP[(r0    )*AST2 + kk0 + tig];
                ahi[mt][1] = AhiP[(r0 + 8)*AST2 + kk0 + tig];
                ahi[mt][2] = AhiP[(r0    )*AST2 + kk0 + tig + 4];
                ahi[mt][3] = AhiP[(r0 + 8)*AST2 + kk0 + tig + 4];
                alo[mt][0] = AloP[(r0    )*AST2 + kk0 + tig];
                alo[mt][1] = AloP[(r0 + 8)*AST2 + kk0 + tig];
                alo[mt][2] = AloP[(r0    )*AST2 + kk0 + tig + 4];
                alo[mt][3] = AloP[(r0 + 8)*AST2 + kk0 + tig + 4];
            }
            #pragma unroll
            for (int nt = 0; nt < 4; nt++) {
                const int nc = warpN + nt*8 + gid;
                unsigned bh0 = WhiP[(kk0 + tig    )*WST2 + nc];
                unsigned bh1 = WhiP[(kk0 + tig + 4)*WST2 + nc];
                unsigned bl0 = WloP[(kk0 + tig    )*WST2 + nc];
                unsigned bl1 = WloP[(kk0 + tig + 4)*WST2 + nc];
                #pragma unroll
                for (int mt = 0; mt < 2; mt++) {
                    mma_bf16(acc[mt][nt], ahi[mt], bh0, bh1);
                    mma_bf16(acc[mt][nt], alo[mt], bh0, bh1);
                    mma_bf16(acc[mt][nt], ahi[mt], bl0, bl1);
                }
            }
        }

        // ---- direct-from-fragment epilogue ----
        #pragma unroll
        for (int mt = 0; mt < 2; mt++) {
            #pragma unroll
            for (int half = 0; half < 2; half++) {
                const int rl = warpM + mt*16 + gid + half*8;
                const int gm = m0 + rl;
                float* orow;
                const float* rrow = 0;
                if (mode == 0)      orow = g_qf + (size_t)((gm & 3)*NPTS + (gm >> 2)) * DD;
                else if (mode == 1) orow = g_kf + (size_t)((gm & 3)*NPTS + (gm >> 2)) * DD;
                else if (mode == 2) orow = g_vf + (size_t)((gm & 3)*NPTS + (gm >> 2)) * DD;
                else if (mode == 3) { orow = outext + (size_t)gm * DD; rrow = resid + (size_t)gm * DD; }
                else if (mode == 4) orow = g_pe + (size_t)gm * DD;
                else                orow = g_h  + (size_t)gm * DD;
                #pragma unroll
                for (int nt = 0; nt < 4; nt++) {
                    const int col = warpN + nt*8 + 2*tig;
                    float2 v;
                    v.x = acc[mt][nt][half*2    ] + sb[col];
                    v.y = acc[mt][nt][half*2 + 1] + sb[col + 1];
                    if (mode == 3) {
                        float2 rr = *(const float2*)(rrow + col);
                        v.x += rr.x; v.y += rr.y;
                    }
                    *(float2*)(orow + col) = v;
                }
            }
        }
    }
}

// ============================================================================
// KNN: 8-way candidate split, shift trick, conflict-free tiles (R9 verbatim)
// ============================================================================
__global__ __launch_bounds__(256, 1) void knn_k(const float* __restrict__ pos)
{
    __shared__ float4 cand[1032];
    __shared__ float  sd[256*8];
    __shared__ int    si[256*8];

    const int b = blockIdx.y;
    const int t = threadIdx.x;
    const int q = blockIdx.x * 32 + (t >> 3);
    const int s = t & 7;
    const float* pb = pos + (size_t)b * NPTS * 3;

    const float qx = pb[q*3], qy = pb[q*3+1], qz = pb[q*3+2];
    const float nx = -2.f*qx, ny = -2.f*qy, nz = -2.f*qz;

    float bd[8]; int bi[8];
    #pragma unroll
    for (int k = 0; k < 8; k++) { bd[k] = 1e30f; bi[k] = 0x7fffffff; }

    const int base = s * 129;
    for (int t0 = 0; t0 < NPTS; t0 += 1024) {
        __syncthreads();
        #pragma unroll
        for (int i = t; i < 1024; i += 256) {
            float x = pb[(t0+i)*3], y = pb[(t0+i)*3+1], z = pb[(t0+i)*3+2];
            cand[i + (i >> 7)] = make_float4(x, y, z, fmaf(z, z, fmaf(y, y, x*x)));
        }
        __syncthreads();
        #pragma unroll 8
        for (int m = 0; m < 128; ++m) {
            float4 c = cand[base + m];
            float sv = fmaf(nx, c.x, fmaf(ny, c.y, fmaf(nz, c.z, c.w)));
            if (sv < bd[7]) {
                bd[7] = sv; bi[7] = t0 + s*128 + m;
                #pragma unroll
                for (int r = 7; r > 0; --r) {
                    if (bd[r] < bd[r-1]) {
                        float td = bd[r]; bd[r] = bd[r-1]; bd[r-1] = td;
                        int   ti = bi[r]; bi[r] = bi[r-1]; bi[r-1] = ti;
                    }
                }
            }
        }
    }

    #pragma unroll
    for (int k = 0; k < 8; k++) { sd[t*8+k] = bd[k]; si[t*8+k] = bi[k]; }
    __syncthreads();

    if (s == 0) {
        int p[8] = {0,0,0,0,0,0,0,0};
        int* op = g_idx + ((size_t)b * NPTS + q) * KK;
        #pragma unroll
        for (int o = 0; o < 8; ++o) {
            float bdv = 1e38f; int biv = 0x7fffffff; int bl = 0;
            #pragma unroll
            for (int l = 0; l < 8; ++l) {
                float dv = sd[(t+l)*8 + p[l]];
                int   iv = si[(t+l)*8 + p[l]];
                if (dv < bdv || (dv == bdv && iv < biv)) { bdv = dv; biv = iv; bl = l; }
            }
            op[o] = biv;
            p[bl]++;
        }
    }
}

// ============================================================================
// build h (float4)
// ============================================================================
__global__ __launch_bounds__(256, 1) void buildh_k(
    const float* __restrict__ pos,
    const float* __restrict__ Wp1, const float* __restrict__ bp1)
{
    const int gid = blockIdx.x * 256 + threadIdx.x;   // < NR*32
    const int r = gid >> 5, d0 = (gid & 31) * 4;
    const int g = r >> 3;
    const int b = g >> 13, n = g & (NPTS - 1);
    const int id = g_idx[r];
    const float* pb = pos + (size_t)b * NPTS * 3;
    const float rx = pb[n*3+0] - pb[id*3+0];
    const float ry = pb[n*3+1] - pb[id*3+1];
    const float rz = pb[n*3+2] - pb[id*3+2];
    const float4 wx = *(const float4*)(Wp1 + d0);
    const float4 wy = *(const float4*)(Wp1 + 128 + d0);
    const float4 wz = *(const float4*)(Wp1 + 256 + d0);
    const float4 bb = *(const float4*)(bp1 + d0);
    float4 o;
    {
        float z = fmaf(rz, wz.x, fmaf(ry, wy.x, fmaf(rx, wx.x, bb.x)));
        o.x = 0.5f * z * (1.f + erff(z * 0.70710678118654752f));
    }
    {
        float z = fmaf(rz, wz.y, fmaf(ry, wy.y, fmaf(rx, wx.y, bb.y)));
        o.y = 0.5f * z * (1.f + erff(z * 0.70710678118654752f));
    }
    {
        float z = fmaf(rz, wz.z, fmaf(ry, wy.z, fmaf(rx, wx.z, bb.z)));
        o.z = 0.5f * z * (1.f + erff(z * 0.70710678118654752f));
    }
    {
        float z = fmaf(rz, wz.w, fmaf(ry, wy.w, fmaf(rx, wx.w, bb.w)));
        o.w = 0.5f * z * (1.f + erff(z * 0.70710678118654752f));
    }
    *(float4*)(g_h + (size_t)r*DD + d0) = o;
}

// ============================================================================
// build u (float4)
// ============================================================================
__global__ __launch_bounds__(256, 1) void buildu_k()
{
    const int gid = blockIdx.x * 256 + threadIdx.x;   // < NR*32
    const int r = gid >> 5, seg = (gid & 31) * 4;
    const int g = r >> 3;
    const int id = g_idx[r];
    const int b = g >> 13;
    float4 qv = *(const float4*)(g_qf + (size_t)g * DD + seg);
    float4 kv = *(const float4*)(g_kf + ((size_t)b * NPTS + id) * DD + seg);
    float4 pe = *(const float4*)(g_pe + (size_t)r * DD + seg);
    float4 u;
    u.x = qv.x - kv.x + pe.x; u.y = qv.y - kv.y + pe.y;
    u.z = qv.z - kv.z + pe.z; u.w = qv.w - kv.w + pe.w;
    *(float4*)(g_u + (size_t)r * DD + seg) = u;
}

// ============================================================================
// finish: per (g,k) row softmax over d of a (= g_h), res = sum_k sm*(v+pe)
// ============================================================================
__global__ __launch_bounds__(256, 1) void finish_k()
{
    __shared__ float rA[2][32];
    __shared__ float rB[2][32];

    const int tid  = threadIdx.x;
    const int grp  = tid >> 7;
    const int d    = tid & 127;
    const int lane = tid & 31;
    const int wsub = (tid >> 5) & 3;
    const int g    = blockIdx.x * 2 + grp;
    const int b    = g >> 13;
    const float scale = 0.08838834764831845f;   // 1/sqrt(128)

    float a[8];
    #pragma unroll
    for (int k = 0; k < 8; ++k)
        a[k] = g_h[((size_t)g*8 + k) * DD + d] * scale;

    float red[8];
    #pragma unroll
    for (int k = 0; k < 8; ++k) red[k] = a[k];
    #pragma unroll
    for (int off = 16; off > 0; off >>= 1)
        #pragma unroll
        for (int k = 0; k < 8; ++k)
            red[k] = fmaxf(red[k], __shfl_xor_sync(0xffffffffu, red[k], off));
    if (lane == 0) {
        #pragma unroll
        for (int k = 0; k < 8; ++k) rA[grp][wsub*8 + k] = red[k];
    }
    __syncthreads();

    float e[8];
    #pragma unroll
    for (int k = 0; k < 8; ++k) {
        float bm = fmaxf(fmaxf(rA[grp][k], rA[grp][8+k]),
                         fmaxf(rA[grp][16+k], rA[grp][24+k]));
        e[k] = __expf(a[k] - bm);
        red[k] = e[k];
    }
    #pragma unroll
    for (int off = 16; off > 0; off >>= 1)
        #pragma unroll
        for (int k = 0; k < 8; ++k)
            red[k] += __shfl_xor_sync(0xffffffffu, red[k], off);
    if (lane == 0) {
        #pragma unroll
        for (int k = 0; k < 8; ++k) rB[grp][wsub*8 + k] = red[k];
    }
    __syncthreads();

    float rsum = 0.f;
    #pragma unroll
    for (int k = 0; k < 8; ++k) {
        float tot = (rB[grp][k] + rB[grp][8+k]) + (rB[grp][16+k] + rB[grp][24+k]);
        float smx = e[k] / tot;
        int id = g_idx[(size_t)g*8 + k];
        float v  = g_vf[((size_t)b * NPTS + id) * DD + d];
        float pe = g_pe[((size_t)g*8 + k) * DD + d];
        rsum = fmaf(smx, v + pe, rsum);
    }
    g_res[(size_t)g * DD + d] = rsum;
}

// ============================================================================
// host launch
// ============================================================================
extern "C" void kernel_launch(void* const* d_in, const int* in_sizes, int n_in,
                              void* d_out, int out_size)
{
    const float* query = (const float*)d_in[0];
    const float* pos   = (const float*)d_in[1];
    const float* Wq  = (const float*)d_in[2];  const float* bq  = (const float*)d_in[3];
    const float* Wk  = (const float*)d_in[4];  const float* bk  = (const float*)d_in[5];
    const float* Wv  = (const float*)d_in[6];  const float* bv  = (const float*)d_in[7];
    const float* Wp1 = (const float*)d_in[8];  const float* bp1 = (const float*)d_in[9];
    const float* Wp2 = (const float*)d_in[10]; const float* bp2 = (const float*)d_in[11];
    const float* Wg  = (const float*)d_in[12]; const float* bg  = (const float*)d_in[13];
    const float* Wo  = (const float*)d_in[14]; const float* bo  = (const float*)d_in[15];
    float* out = (float*)d_out;

    cudaFuncSetAttribute(gemm_mma, cudaFuncAttributeMaxDynamicSharedMemorySize, SMEM_BYTES);

    int dev = 0, sms = 148;
    cudaGetDevice(&dev);
    cudaDeviceGetAttribute(&sms, cudaDevAttrMultiProcessorCount, dev);

    const int NT_NB = NB/128;   // 256
    const int NT_NR = NR/128;   // 2048
    const int gNB = (NT_NB < sms) ? NT_NB : sms;
    const int gNR = sms;

    // KNN first (longest independent kernel)
    knn_k<<<dim3(NPTS/32, BB), 256>>>(pos);

    // QKV projections -> g_qf/g_kf/g_vf in [B,N,D]
    gemm_mma<<<gNB, THREADS, SMEM_BYTES>>>(query, Wq, bq, 0, 0, NT_NB, 0);
    gemm_mma<<<gNB, THREADS, SMEM_BYTES>>>(query, Wk, bk, 0, 0, NT_NB, 1);
    gemm_mma<<<gNB, THREADS, SMEM_BYTES>>>(query, Wv, bv, 0, 0, NT_NB, 2);

    // h = gelu(lin1(rel))          [NR,128]
    buildh_k<<<NR*32/256, 256>>>(pos, Wp1, bp1);

    // pe = h @ Wp2 + bp2           [NR,128]
    gemm_mma<<<gNR, THREADS, SMEM_BYTES>>>(0, Wp2, bp2, 0, 0, NT_NR, 4);

    // u = q - k_knn + pe           [NR,128]
    buildu_k<<<NR*32/256, 256>>>();

    // a = u @ Wg + bg              [NR,128]  (into g_h)
    gemm_mma<<<gNR, THREADS, SMEM_BYTES>>>(0, Wg, bg, 0, 0, NT_NR, 5);

    // softmax over d + weighted sum over k -> g_res [B,N,D]
    finish_k<<<NB/2, 256>>>();

    // out = res@Wo + bo + query    [N,B,D]
    gemm_mma<<<gNB, THREADS, SMEM_BYTES>>>(query, Wo, bo, query, out, NT_NB, 3);
}